// round 1
// baseline (speedup 1.0000x reference)
#include <cuda_runtime.h>
#include <cstdint>

#define BDIM 8192
#define DDIM 1024
#define EDIM 32
#define ADIM 128

// scratch: softmax gating weights [B, E]
__device__ float g_weights[BDIM * EDIM];

// ---------------------------------------------------------------------------
// Kernel 1: gating.  logits = x @ W_att^T + b_att + adaptive_bias,
// add gumbel noise, softmax over E=32 -> g_weights.
// One warp per row; x row cached in registers (32 floats/lane).
// ---------------------------------------------------------------------------
__global__ __launch_bounds__(256) void gating_kernel(
    const float* __restrict__ x,
    const float* __restrict__ W_att,
    const float* __restrict__ b_att,
    const float* __restrict__ adaptive_bias,
    const float* __restrict__ gumbel_u)
{
    const int warp = threadIdx.x >> 5;
    const int lane = threadIdx.x & 31;
    const int b = blockIdx.x * 8 + warp;

    __shared__ float logits_s[8][EDIM];

    const float* xrow = x + (size_t)b * DDIM;
    float xr[32];
#pragma unroll
    for (int k = 0; k < 32; k++) xr[k] = xrow[k * 32 + lane];

    for (int e = 0; e < EDIM; e++) {
        const float* wrow = W_att + (size_t)e * DDIM;
        float p = 0.f;
#pragma unroll
        for (int k = 0; k < 32; k++) p = fmaf(xr[k], wrow[k * 32 + lane], p);
#pragma unroll
        for (int o = 16; o; o >>= 1) p += __shfl_xor_sync(0xffffffffu, p, o);
        if (lane == 0) logits_s[warp][e] = p;
    }
    __syncwarp();

    // softmax over 32 lanes (lane == e)
    float l = logits_s[warp][lane] + b_att[lane] + adaptive_bias[lane];
    float u = gumbel_u[(size_t)b * EDIM + lane];
    float g = -logf(-logf(u + 1e-10f) + 1e-10f);
    float z = l + g;  // TAU == 1.0

    float m = z;
#pragma unroll
    for (int o = 16; o; o >>= 1) m = fmaxf(m, __shfl_xor_sync(0xffffffffu, m, o));
    float p = expf(z - m);
    float s = p;
#pragma unroll
    for (int o = 16; o; o >>= 1) s += __shfl_xor_sync(0xffffffffu, s, o);

    g_weights[(size_t)b * EDIM + lane] = p / s;
}

// ---------------------------------------------------------------------------
// Kernel 2: fused strategy superposition.
// out[b,a] = sum_e w[b,e] * ( x[b,:] . W_strat[e,a,:] + b_strat[e,a] )
// Block tile 64x128 (BM x A), BK=32, 256 threads, thread tile 4x8.
// Accumulators held as packed f32x2; inner loop uses fma.rn.f32x2 (2x FFMA rate).
// Per-e partial accumulated over full D, then folded by w[b,e].
// Register-prefetch pipeline hides L2 latency (1 block/SM).
// ---------------------------------------------------------------------------
__device__ __forceinline__ unsigned long long pack2(float v) {
    unsigned long long r;
    asm("mov.b64 %0, {%1, %1};" : "=l"(r) : "f"(v));
    return r;
}
__device__ __forceinline__ void ffma2(unsigned long long& d,
                                      unsigned long long a,
                                      unsigned long long b) {
    asm("fma.rn.f32x2 %0, %1, %2, %0;" : "+l"(d) : "l"(a), "l"(b));
}

#define BM 64
#define BK 32
#define XS_STRIDE 68   // BM + 4 pad: 272B row stride (16B multiple, fewer STS conflicts)
#define WS_STRIDE 132  // ADIM + 4 pad: 528B row stride

__global__ __launch_bounds__(256) void super_kernel(
    const float* __restrict__ x,
    const float* __restrict__ W_strat,
    const float* __restrict__ b_strat,
    float* __restrict__ out)
{
    __shared__ __align__(16) float xs[BK][XS_STRIDE];
    __shared__ __align__(16) float ws[BK][WS_STRIDE];

    const int tid = threadIdx.x;
    const int tr = tid >> 4;   // 0..15 -> rows tr*4 .. tr*4+3
    const int tc = tid & 15;   // 0..15 -> cols tc*8 .. tc*8+7
    const int row0 = blockIdx.x * BM;

    const int lr = tid >> 3;        // 0..31 (load row base)
    const int ld4 = (tid & 7) * 4;  // 0,4,...,28 (load d offset, float4)

    const float* xb = x + (size_t)row0 * DDIM;

    unsigned long long acc[4][4];
    unsigned long long acce[4][4];
#pragma unroll
    for (int i = 0; i < 4; i++)
#pragma unroll
        for (int p = 0; p < 4; p++) acc[i][p] = 0ull;

    float4 px[2], pw[4];

    // prologue: prefetch first tiles (e=0, dk=0)
#pragma unroll
    for (int i = 0; i < 2; i++)
        px[i] = *(const float4*)&xb[(size_t)(lr + 32 * i) * DDIM + ld4];
#pragma unroll
    for (int i = 0; i < 4; i++)
        pw[i] = *(const float4*)&W_strat[(size_t)(lr + 32 * i) * DDIM + ld4];

    const int ITERS = EDIM * (DDIM / BK);  // 1024
    for (int it = 0; it < ITERS; it++) {
        const int e = it >> 5;
        const int kslot = it & 31;

        // stage prefetched tiles into smem
#pragma unroll
        for (int i = 0; i < 2; i++) {
            const int r = lr + 32 * i;
            xs[ld4 + 0][r] = px[i].x;
            xs[ld4 + 1][r] = px[i].y;
            xs[ld4 + 2][r] = px[i].z;
            xs[ld4 + 3][r] = px[i].w;
        }
#pragma unroll
        for (int i = 0; i < 4; i++) {
            const int a = lr + 32 * i;
            ws[ld4 + 0][a] = pw[i].x;
            ws[ld4 + 1][a] = pw[i].y;
            ws[ld4 + 2][a] = pw[i].z;
            ws[ld4 + 3][a] = pw[i].w;
        }
        __syncthreads();

        // prefetch next tiles (overlaps with compute below)
        if (it + 1 < ITERS) {
            const int itn = it + 1;
            const int en = itn >> 5;
            const int dkn = (itn & 31) * BK;
            const float* Wb = W_strat + (size_t)en * ADIM * DDIM;
#pragma unroll
            for (int i = 0; i < 2; i++)
                px[i] = *(const float4*)&xb[(size_t)(lr + 32 * i) * DDIM + dkn + ld4];
#pragma unroll
            for (int i = 0; i < 4; i++)
                pw[i] = *(const float4*)&Wb[(size_t)(lr + 32 * i) * DDIM + dkn + ld4];
        }

        if (kslot == 0) {
#pragma unroll
            for (int i = 0; i < 4; i++)
#pragma unroll
                for (int p = 0; p < 4; p++) acce[i][p] = 0ull;
        }

        // compute: 32 k-steps, 16 ffma2 each per thread
#pragma unroll
        for (int dd = 0; dd < BK; dd++) {
            const float4 xa = *(const float4*)&xs[dd][tr * 4];
            const ulonglong2 w0 = *(const ulonglong2*)&ws[dd][tc * 8];
            const ulonglong2 w1 = *(const ulonglong2*)&ws[dd][tc * 8 + 4];
            const float xf[4] = {xa.x, xa.y, xa.z, xa.w};
#pragma unroll
            for (int i = 0; i < 4; i++) {
                const unsigned long long xx = pack2(xf[i]);
                ffma2(acce[i][0], xx, w0.x);
                ffma2(acce[i][1], xx, w0.y);
                ffma2(acce[i][2], xx, w1.x);
                ffma2(acce[i][3], xx, w1.y);
            }
        }
        __syncthreads();

        // end of this e's D loop: fold partial into final with gating weight
        if (kslot == 31) {
            float wgt[4];
#pragma unroll
            for (int i = 0; i < 4; i++)
                wgt[i] = g_weights[(size_t)(row0 + tr * 4 + i) * EDIM + e];
            const float* bsrow = b_strat + (size_t)e * ADIM + tc * 8;
#pragma unroll
            for (int i = 0; i < 4; i++) {
#pragma unroll
                for (int p = 0; p < 4; p++) {
                    float2 t = *reinterpret_cast<float2*>(&acce[i][p]);
                    float2 a = *reinterpret_cast<float2*>(&acc[i][p]);
                    a.x = fmaf(wgt[i], t.x + bsrow[2 * p + 0], a.x);
                    a.y = fmaf(wgt[i], t.y + bsrow[2 * p + 1], a.y);
                    *reinterpret_cast<float2*>(&acc[i][p]) = a;
                }
            }
        }
    }

    // write out[64 x 128] tile
#pragma unroll
    for (int i = 0; i < 4; i++) {
        const size_t row = (size_t)(row0 + tr * 4 + i);
        ulonglong2* o0 = (ulonglong2*)&out[row * ADIM + tc * 8];
        ulonglong2* o1 = (ulonglong2*)&out[row * ADIM + tc * 8 + 4];
        *o0 = make_ulonglong2(acc[i][0], acc[i][1]);
        *o1 = make_ulonglong2(acc[i][2], acc[i][3]);
    }
}

// ---------------------------------------------------------------------------
extern "C" void kernel_launch(void* const* d_in, const int* in_sizes, int n_in,
                              void* d_out, int out_size) {
    const float* x             = (const float*)d_in[0];
    const float* W_att         = (const float*)d_in[1];
    const float* b_att         = (const float*)d_in[2];
    const float* adaptive_bias = (const float*)d_in[3];
    const float* W_strat       = (const float*)d_in[4];
    const float* b_strat       = (const float*)d_in[5];
    const float* gumbel_u      = (const float*)d_in[6];
    float* out = (float*)d_out;

    gating_kernel<<<BDIM / 8, 256>>>(x, W_att, b_att, adaptive_bias, gumbel_u);
    super_kernel<<<BDIM / BM, 256>>>(x, W_strat, b_strat, out);
}

// round 6
// speedup vs baseline: 4.8013x; 4.8013x over previous
#include <cuda_runtime.h>
#include <cstdint>

#define BDIM 8192
#define DDIM 1024
#define EDIM 32
#define ADIM 128
#define EG   4
#define NGRP (EDIM / EG)     // 8
#define BM   128
#define BN   128
#define BK   32              // 32 fp32 = 128 B per smem row (SW128 atom width)
#define NKB  (DDIM / BK)     // 32
#define TILE_BYTES (BM * BK * 4)        // 16384
#define STAGE      (2 * TILE_BYTES)     // A + B
#define SMEM_DYN   (2 * STAGE)          // 65536 double buffered

// ---------------- device scratch (static; no allocs allowed) ----------------
__device__ __align__(1024) float g_Xtf[(size_t)BDIM * DDIM];          // 33.5 MB (tf32-rounded)
__device__ __align__(1024) float g_Wtf[(size_t)EDIM * ADIM * DDIM];   // 16.8 MB (tf32-rounded)
__device__ float g_weights[BDIM * EDIM];                              // 1 MB
__device__ float g_scratch[(size_t)NGRP * BDIM * ADIM];               // 33.5 MB

// ---------------- helpers ----------------
__device__ __forceinline__ uint32_t smem_u32(const void* p) {
    uint32_t a;
    asm("{ .reg .u64 t; cvta.to.shared.u64 t, %1; cvt.u32.u64 %0, t; }" : "=r"(a) : "l"(p));
    return a;
}
__device__ __forceinline__ void cp_async16(uint32_t dst, const void* src) {
    asm volatile("cp.async.cg.shared.global [%0], [%1], 16;" :: "r"(dst), "l"(src));
}
__device__ __forceinline__ void cp_commit() { asm volatile("cp.async.commit_group;"); }
__device__ __forceinline__ void cp_wait0()  { asm volatile("cp.async.wait_group 0;" ::: "memory"); }
__device__ __forceinline__ void cp_wait1()  { asm volatile("cp.async.wait_group 1;" ::: "memory"); }
__device__ __forceinline__ uint32_t sw128(uint32_t o) { return o ^ ((o >> 3) & 0x70); }
__device__ __forceinline__ uint32_t f2tf32(float v) {
    uint32_t t;
    asm("cvt.rna.tf32.f32 %0, %1;" : "=r"(t) : "f"(v));
    return t;
}
__device__ __forceinline__ void mma_tf32(float d[4], const uint32_t a[4], const uint32_t b[2]) {
    asm volatile(
        "mma.sync.aligned.m16n8k8.row.col.f32.tf32.tf32.f32 "
        "{%0,%1,%2,%3}, {%4,%5,%6,%7}, {%8,%9}, {%0,%1,%2,%3};"
        : "+f"(d[0]), "+f"(d[1]), "+f"(d[2]), "+f"(d[3])
        : "r"(a[0]), "r"(a[1]), "r"(a[2]), "r"(a[3]), "r"(b[0]), "r"(b[1]));
}

// ---------------------------------------------------------------------------
// Gating (validated in R1): logits + gumbel + softmax -> g_weights
// ---------------------------------------------------------------------------
__global__ __launch_bounds__(256) void gating_kernel(
    const float* __restrict__ x, const float* __restrict__ W_att,
    const float* __restrict__ b_att, const float* __restrict__ adaptive_bias,
    const float* __restrict__ gumbel_u)
{
    const int warp = threadIdx.x >> 5, lane = threadIdx.x & 31;
    const int b = blockIdx.x * 8 + warp;
    __shared__ float logits_s[8][EDIM];

    const float* xrow = x + (size_t)b * DDIM;
    float xr[32];
#pragma unroll
    for (int k = 0; k < 32; k++) xr[k] = xrow[k * 32 + lane];

    for (int e = 0; e < EDIM; e++) {
        const float* wrow = W_att + (size_t)e * DDIM;
        float p = 0.f;
#pragma unroll
        for (int k = 0; k < 32; k++) p = fmaf(xr[k], wrow[k * 32 + lane], p);
#pragma unroll
        for (int o = 16; o; o >>= 1) p += __shfl_xor_sync(0xffffffffu, p, o);
        if (lane == 0) logits_s[warp][e] = p;
    }
    __syncwarp();

    float l = logits_s[warp][lane] + b_att[lane] + adaptive_bias[lane];
    float u = gumbel_u[(size_t)b * EDIM + lane];
    float g = -logf(-logf(u + 1e-10f) + 1e-10f);
    float z = l + g;
    float m = z;
#pragma unroll
    for (int o = 16; o; o >>= 1) m = fmaxf(m, __shfl_xor_sync(0xffffffffu, m, o));
    float p = expf(z - m);
    float s = p;
#pragma unroll
    for (int o = 16; o; o >>= 1) s += __shfl_xor_sync(0xffffffffu, s, o);
    g_weights[(size_t)b * EDIM + lane] = p / s;
}

// ---------------------------------------------------------------------------
// Pre-round x and W_strat to tf32 precision (stored as f32 bits)
// ---------------------------------------------------------------------------
__global__ __launch_bounds__(256) void convert_x_tf(const float* __restrict__ x) {
    const size_t i4 = (size_t)blockIdx.x * 256 + threadIdx.x;
    float4 v = ((const float4*)x)[i4];
    uint4 o;
    o.x = f2tf32(v.x); o.y = f2tf32(v.y); o.z = f2tf32(v.z); o.w = f2tf32(v.w);
    ((uint4*)g_Xtf)[i4] = o;
}
__global__ __launch_bounds__(256) void convert_w_tf(const float* __restrict__ W_strat) {
    const size_t i4 = (size_t)blockIdx.x * 256 + threadIdx.x;
    float4 v = ((const float4*)W_strat)[i4];
    uint4 o;
    o.x = f2tf32(v.x); o.y = f2tf32(v.y); o.z = f2tf32(v.z); o.w = f2tf32(v.w);
    ((uint4*)g_Wtf)[i4] = o;
}

// ---------------------------------------------------------------------------
// TF32 mma.sync GEMM, fused epilogue.
// CTA = (mt, eg): 128 rows x 128 A-cols x 4 experts (sequential).
// cp.async double-buffered BK=32 tiles; 8 warps (4m x 2n), warp tile 32x64.
// ---------------------------------------------------------------------------
__global__ __launch_bounds__(256) void gemm_tf32(const float* __restrict__ b_strat) {
    extern __shared__ char sm[];
    __shared__ float bs_s[EG][BN];
    __shared__ float w_s[EG][BM];

    const int tid = threadIdx.x, wid = tid >> 5, lane = tid & 31;
    const int wm = wid & 3, wn = wid >> 2;          // warp grid 4x2
    const int eg = blockIdx.x & (NGRP - 1);
    const int mt = blockIdx.x >> 3;
    const int row0 = mt * BM;

    // stage bias + gating weights for this CTA
    for (int i = tid; i < EG * BN; i += 256)
        (&bs_s[0][0])[i] = b_strat[(size_t)(eg * EG) * ADIM + i];
    for (int i = tid; i < EG * BM; i += 256) {
        const int e = i >> 7, r = i & 127;
        w_s[e][r] = g_weights[(size_t)(row0 + r) * EDIM + eg * EG + e];
    }

    const uint32_t sbase = smem_u32(sm);

    auto load_stage = [&](int b, int e, int kb) {
        const uint32_t ab = sbase + b * STAGE;
        const char* xs = (const char*)g_Xtf + ((size_t)row0 * DDIM + kb * BK) * 4;
#pragma unroll
        for (int i = 0; i < 4; i++) {
            const int q = tid + 256 * i, r = q >> 3, ch = (q & 7) * 16;
            cp_async16(ab + sw128(r * 128 + ch), xs + (size_t)r * DDIM * 4 + ch);
        }
        const uint32_t bb = ab + TILE_BYTES;
        const char* ws = (const char*)g_Wtf +
                         ((size_t)(eg * EG + e) * ADIM * DDIM + kb * BK) * 4;
#pragma unroll
        for (int i = 0; i < 4; i++) {
            const int q = tid + 256 * i, r = q >> 3, ch = (q & 7) * 16;
            cp_async16(bb + sw128(r * 128 + ch), ws + (size_t)r * DDIM * 4 + ch);
        }
        cp_commit();
    };

    float accf[2][8][4];
#pragma unroll
    for (int f = 0; f < 2; f++)
#pragma unroll
        for (int j = 0; j < 8; j++)
#pragma unroll
            for (int d = 0; d < 4; d++) accf[f][j][d] = 0.f;

    load_stage(0, 0, 0);

    for (int e = 0; e < EG; e++) {
        float acce[2][8][4];
#pragma unroll
        for (int f = 0; f < 2; f++)
#pragma unroll
            for (int j = 0; j < 8; j++)
#pragma unroll
                for (int d = 0; d < 4; d++) acce[f][j][d] = 0.f;

        for (int kb = 0; kb < NKB; kb++) {
            const int t = e * NKB + kb;
            const int buf = t & 1;
            const bool more = (t + 1 < EG * NKB);
            if (more) load_stage(buf ^ 1, (t + 1) >> 5, (t + 1) & 31);
            if (more) cp_wait1(); else cp_wait0();
            __syncthreads();

            const uint32_t ab = sbase + buf * STAGE;
            const uint32_t bb = ab + TILE_BYTES;
#pragma unroll
            for (int ks = 0; ks < 4; ks++) {
                // A fragments: 2x ldmatrix.x4 (rows wm*32 .. +31)
                uint32_t afr[2][4];
#pragma unroll
                for (int f = 0; f < 2; f++) {
                    const int m0 = wm * 32 + f * 16;
                    const uint32_t row = m0 + (lane & 15);
                    const uint32_t byt = ks * 32 + (lane >> 4) * 16;
                    const uint32_t addr = ab + sw128(row * 128 + byt);
                    asm volatile(
                        "ldmatrix.sync.aligned.m8n8.x4.shared.b16 {%0,%1,%2,%3}, [%4];"
                        : "=r"(afr[f][0]), "=r"(afr[f][1]), "=r"(afr[f][2]), "=r"(afr[f][3])
                        : "r"(addr));
                }
                // B fragments: 4x ldmatrix.x4, each covers two n8 tiles
                uint32_t bfr[4][4];
#pragma unroll
                for (int jp = 0; jp < 4; jp++) {
                    const int n0 = wn * 64 + jp * 16;
                    const uint32_t row = n0 + ((lane >> 4) & 1) * 8 + (lane & 7);
                    const uint32_t byt = ks * 32 + ((lane >> 3) & 1) * 16;
                    const uint32_t addr = bb + sw128(row * 128 + byt);
                    asm volatile(
                        "ldmatrix.sync.aligned.m8n8.x4.shared.b16 {%0,%1,%2,%3}, [%4];"
                        : "=r"(bfr[jp][0]), "=r"(bfr[jp][1]), "=r"(bfr[jp][2]), "=r"(bfr[jp][3])
                        : "r"(addr));
                }
#pragma unroll
                for (int f = 0; f < 2; f++)
#pragma unroll
                    for (int jp = 0; jp < 4; jp++) {
                        mma_tf32(acce[f][2 * jp + 0], afr[f], &bfr[jp][0]);
                        mma_tf32(acce[f][2 * jp + 1], afr[f], &bfr[jp][2]);
                    }
            }
            __syncthreads();
        }

        // fold expert e: accf += w[row,e] * (acce + bias[col])
#pragma unroll
        for (int f = 0; f < 2; f++) {
            const int r1 = wm * 32 + f * 16 + (lane >> 2);
            const float w1 = w_s[e][r1], w2 = w_s[e][r1 + 8];
#pragma unroll
            for (int j = 0; j < 8; j++) {
                const int c0 = wn * 64 + j * 8 + (lane & 3) * 2;
                const float b0 = bs_s[e][c0], b1 = bs_s[e][c0 + 1];
                accf[f][j][0] = fmaf(w1, acce[f][j][0] + b0, accf[f][j][0]);
                accf[f][j][1] = fmaf(w1, acce[f][j][1] + b1, accf[f][j][1]);
                accf[f][j][2] = fmaf(w2, acce[f][j][2] + b0, accf[f][j][2]);
                accf[f][j][3] = fmaf(w2, acce[f][j][3] + b1, accf[f][j][3]);
            }
        }
    }

    // write to per-group scratch
#pragma unroll
    for (int f = 0; f < 2; f++) {
        const int r1 = row0 + wm * 32 + f * 16 + (lane >> 2);
#pragma unroll
        for (int j = 0; j < 8; j++) {
            const int c0 = wn * 64 + j * 8 + (lane & 3) * 2;
            float* base = g_scratch + (size_t)eg * BDIM * ADIM;
            *(float2*)&base[(size_t)r1 * ADIM + c0] =
                make_float2(accf[f][j][0], accf[f][j][1]);
            *(float2*)&base[(size_t)(r1 + 8) * ADIM + c0] =
                make_float2(accf[f][j][2], accf[f][j][3]);
        }
    }
}

// ---------------------------------------------------------------------------
// Final reduce: out = sum over 8 expert-group partials
// ---------------------------------------------------------------------------
__global__ __launch_bounds__(256) void reduce_kernel(float* __restrict__ out) {
    const size_t idx = (size_t)blockIdx.x * 256 + threadIdx.x;
    const float4* s = (const float4*)g_scratch;
    float4 a = s[idx];
#pragma unroll
    for (int g = 1; g < NGRP; g++) {
        float4 t = s[(size_t)g * (BDIM * ADIM / 4) + idx];
        a.x += t.x; a.y += t.y; a.z += t.z; a.w += t.w;
    }
    ((float4*)out)[idx] = a;
}

// ---------------------------------------------------------------------------
extern "C" void kernel_launch(void* const* d_in, const int* in_sizes, int n_in,
                              void* d_out, int out_size) {
    const float* x             = (const float*)d_in[0];
    const float* W_att         = (const float*)d_in[1];
    const float* b_att         = (const float*)d_in[2];
    const float* adaptive_bias = (const float*)d_in[3];
    const float* W_strat       = (const float*)d_in[4];
    const float* b_strat       = (const float*)d_in[5];
    const float* gumbel_u      = (const float*)d_in[6];
    float* out = (float*)d_out;

    cudaFuncSetAttribute(gemm_tf32, cudaFuncAttributeMaxDynamicSharedMemorySize, SMEM_DYN);

    gating_kernel<<<BDIM / 8, 256>>>(x, W_att, b_att, adaptive_bias, gumbel_u);
    convert_x_tf<<<(BDIM * DDIM / 4) / 256, 256>>>(x);
    convert_w_tf<<<(EDIM * ADIM * DDIM / 4) / 256, 256>>>(W_strat);
    gemm_tf32<<<(BDIM / BM) * NGRP, 256, SMEM_DYN>>>(b_strat);
    reduce_kernel<<<(BDIM * ADIM / 4) / 256, 256>>>(out);
}

// round 7
// speedup vs baseline: 4.9371x; 1.0283x over previous
#include <cuda_runtime.h>
#include <cstdint>

#define BDIM 8192
#define DDIM 1024
#define EDIM 32
#define ADIM 128
#define EG   4
#define NGRP (EDIM / EG)     // 8
#define BM   128
#define BN   128
#define BK   32              // 32 fp32 = 128 B per smem row (SW128 atom width)
#define NKB  (DDIM / BK)     // 32
#define THREADS 512
#define TILE_BYTES (BM * BK * 4)        // 16384
#define STAGE      (2 * TILE_BYTES)     // A + B
#define SMEM_DYN   (2 * STAGE)          // 65536 double buffered

// ---------------- device scratch (static; no allocs allowed) ----------------
__device__ __align__(1024) float g_Xtf[(size_t)BDIM * DDIM];          // tf32-rounded x
__device__ __align__(1024) float g_Wtf[(size_t)EDIM * ADIM * DDIM];   // tf32-rounded W_strat
__device__ float g_weights[BDIM * EDIM];
__device__ float g_scratch[(size_t)NGRP * BDIM * ADIM];

// ---------------- helpers ----------------
__device__ __forceinline__ uint32_t smem_u32(const void* p) {
    uint32_t a;
    asm("{ .reg .u64 t; cvta.to.shared.u64 t, %1; cvt.u32.u64 %0, t; }" : "=r"(a) : "l"(p));
    return a;
}
__device__ __forceinline__ void cp_async16(uint32_t dst, const void* src) {
    asm volatile("cp.async.cg.shared.global [%0], [%1], 16;" :: "r"(dst), "l"(src));
}
__device__ __forceinline__ void cp_commit() { asm volatile("cp.async.commit_group;"); }
__device__ __forceinline__ void cp_wait0()  { asm volatile("cp.async.wait_group 0;" ::: "memory"); }
__device__ __forceinline__ void cp_wait1()  { asm volatile("cp.async.wait_group 1;" ::: "memory"); }
__device__ __forceinline__ uint32_t sw128(uint32_t o) { return o ^ ((o >> 3) & 0x70); }
__device__ __forceinline__ uint32_t f2tf32(float v) {
    uint32_t t;
    asm("cvt.rna.tf32.f32 %0, %1;" : "=r"(t) : "f"(v));
    return t;
}
__device__ __forceinline__ void mma_tf32(float d[4], const uint32_t a[4], const uint32_t b[2]) {
    asm volatile(
        "mma.sync.aligned.m16n8k8.row.col.f32.tf32.tf32.f32 "
        "{%0,%1,%2,%3}, {%4,%5,%6,%7}, {%8,%9}, {%0,%1,%2,%3};"
        : "+f"(d[0]), "+f"(d[1]), "+f"(d[2]), "+f"(d[3])
        : "r"(a[0]), "r"(a[1]), "r"(a[2]), "r"(a[3]), "r"(b[0]), "r"(b[1]));
}

// ---------------------------------------------------------------------------
// Gating: logits + gumbel + softmax -> g_weights
// ---------------------------------------------------------------------------
__global__ __launch_bounds__(256) void gating_kernel(
    const float* __restrict__ x, const float* __restrict__ W_att,
    const float* __restrict__ b_att, const float* __restrict__ adaptive_bias,
    const float* __restrict__ gumbel_u)
{
    const int warp = threadIdx.x >> 5, lane = threadIdx.x & 31;
    const int b = blockIdx.x * 8 + warp;
    __shared__ float logits_s[8][EDIM];

    const float* xrow = x + (size_t)b * DDIM;
    float xr[32];
#pragma unroll
    for (int k = 0; k < 32; k++) xr[k] = xrow[k * 32 + lane];

    for (int e = 0; e < EDIM; e++) {
        const float* wrow = W_att + (size_t)e * DDIM;
        float p = 0.f;
#pragma unroll
        for (int k = 0; k < 32; k++) p = fmaf(xr[k], wrow[k * 32 + lane], p);
#pragma unroll
        for (int o = 16; o; o >>= 1) p += __shfl_xor_sync(0xffffffffu, p, o);
        if (lane == 0) logits_s[warp][e] = p;
    }
    __syncwarp();

    float l = logits_s[warp][lane] + b_att[lane] + adaptive_bias[lane];
    float u = gumbel_u[(size_t)b * EDIM + lane];
    float g = -logf(-logf(u + 1e-10f) + 1e-10f);
    float z = l + g;
    float m = z;
#pragma unroll
    for (int o = 16; o; o >>= 1) m = fmaxf(m, __shfl_xor_sync(0xffffffffu, m, o));
    float p = expf(z - m);
    float s = p;
#pragma unroll
    for (int o = 16; o; o >>= 1) s += __shfl_xor_sync(0xffffffffu, s, o);
    g_weights[(size_t)b * EDIM + lane] = p / s;
}

// ---------------------------------------------------------------------------
// Pre-round x and W_strat to tf32 precision (stored as f32 bits)
// ---------------------------------------------------------------------------
__global__ __launch_bounds__(256) void convert_x_tf(const float* __restrict__ x) {
    const size_t i4 = (size_t)blockIdx.x * 256 + threadIdx.x;
    float4 v = ((const float4*)x)[i4];
    uint4 o;
    o.x = f2tf32(v.x); o.y = f2tf32(v.y); o.z = f2tf32(v.z); o.w = f2tf32(v.w);
    ((uint4*)g_Xtf)[i4] = o;
}
__global__ __launch_bounds__(256) void convert_w_tf(const float* __restrict__ W_strat) {
    const size_t i4 = (size_t)blockIdx.x * 256 + threadIdx.x;
    float4 v = ((const float4*)W_strat)[i4];
    uint4 o;
    o.x = f2tf32(v.x); o.y = f2tf32(v.y); o.z = f2tf32(v.z); o.w = f2tf32(v.w);
    ((uint4*)g_Wtf)[i4] = o;
}

// ---------------------------------------------------------------------------
// TF32 mma.sync GEMM, fused epilogue.
// CTA = (mt, eg): 128 rows x 128 A-cols x 4 experts (sequential).
// 512 threads, 16 warps (4m x 4n), warp tile 32x32.
// ---------------------------------------------------------------------------
__global__ __launch_bounds__(THREADS) void gemm_tf32(const float* __restrict__ b_strat) {
    extern __shared__ char sm[];
    __shared__ float bs_s[EG][BN];
    __shared__ float w_s[EG][BM];

    const int tid = threadIdx.x, wid = tid >> 5, lane = tid & 31;
    const int wm = wid & 3, wn = wid >> 2;          // warp grid 4m x 4n
    const int eg = blockIdx.x & (NGRP - 1);
    const int mt = blockIdx.x >> 3;
    const int row0 = mt * BM;

    // stage bias + gating weights (EG*128 = 512 elements each, one per thread)
    {
        (&bs_s[0][0])[tid] = b_strat[(size_t)(eg * EG) * ADIM + tid];
        const int e = tid >> 7, r = tid & 127;
        w_s[e][r] = g_weights[(size_t)(row0 + r) * EDIM + eg * EG + e];
    }

    const uint32_t sbase = smem_u32(sm);

    auto load_stage = [&](int b, int e, int kb) {
        const uint32_t ab = sbase + b * STAGE;
        const char* xs = (const char*)g_Xtf + ((size_t)row0 * DDIM + kb * BK) * 4;
#pragma unroll
        for (int i = 0; i < 2; i++) {
            const int q = tid + THREADS * i, r = q >> 3, ch = (q & 7) * 16;
            cp_async16(ab + sw128(r * 128 + ch), xs + (size_t)r * DDIM * 4 + ch);
        }
        const uint32_t bb = ab + TILE_BYTES;
        const char* ws = (const char*)g_Wtf +
                         ((size_t)(eg * EG + e) * ADIM * DDIM + kb * BK) * 4;
#pragma unroll
        for (int i = 0; i < 2; i++) {
            const int q = tid + THREADS * i, r = q >> 3, ch = (q & 7) * 16;
            cp_async16(bb + sw128(r * 128 + ch), ws + (size_t)r * DDIM * 4 + ch);
        }
        cp_commit();
    };

    float accf[2][4][4];
#pragma unroll
    for (int f = 0; f < 2; f++)
#pragma unroll
        for (int j = 0; j < 4; j++)
#pragma unroll
            for (int d = 0; d < 4; d++) accf[f][j][d] = 0.f;

    load_stage(0, 0, 0);

    for (int e = 0; e < EG; e++) {
        float acce[2][4][4];
#pragma unroll
        for (int f = 0; f < 2; f++)
#pragma unroll
            for (int j = 0; j < 4; j++)
#pragma unroll
                for (int d = 0; d < 4; d++) acce[f][j][d] = 0.f;

        for (int kb = 0; kb < NKB; kb++) {
            const int t = e * NKB + kb;
            const int buf = t & 1;
            const bool more = (t + 1 < EG * NKB);
            if (more) load_stage(buf ^ 1, (t + 1) >> 5, (t + 1) & 31);
            if (more) cp_wait1(); else cp_wait0();
            __syncthreads();

            const uint32_t ab = sbase + buf * STAGE;
            const uint32_t bb = ab + TILE_BYTES;
#pragma unroll
            for (int ks = 0; ks < 4; ks++) {
                uint32_t afr[2][4];
#pragma unroll
                for (int f = 0; f < 2; f++) {
                    const int m0 = wm * 32 + f * 16;
                    const uint32_t row = m0 + (lane & 15);
                    const uint32_t byt = ks * 32 + (lane >> 4) * 16;
                    const uint32_t addr = ab + sw128(row * 128 + byt);
                    asm volatile(
                        "ldmatrix.sync.aligned.m8n8.x4.shared.b16 {%0,%1,%2,%3}, [%4];"
                        : "=r"(afr[f][0]), "=r"(afr[f][1]), "=r"(afr[f][2]), "=r"(afr[f][3])
                        : "r"(addr));
                }
                uint32_t bfr[2][4];
#pragma unroll
                for (int jp = 0; jp < 2; jp++) {
                    const int n0 = wn * 32 + jp * 16;
                    const uint32_t row = n0 + ((lane >> 4) & 1) * 8 + (lane & 7);
                    const uint32_t byt = ks * 32 + ((lane >> 3) & 1) * 16;
                    const uint32_t addr = bb + sw128(row * 128 + byt);
                    asm volatile(
                        "ldmatrix.sync.aligned.m8n8.x4.shared.b16 {%0,%1,%2,%3}, [%4];"
                        : "=r"(bfr[jp][0]), "=r"(bfr[jp][1]), "=r"(bfr[jp][2]), "=r"(bfr[jp][3])
                        : "r"(addr));
                }
#pragma unroll
                for (int f = 0; f < 2; f++)
#pragma unroll
                    for (int jp = 0; jp < 2; jp++) {
                        mma_tf32(acce[f][2 * jp + 0], afr[f], &bfr[jp][0]);
                        mma_tf32(acce[f][2 * jp + 1], afr[f], &bfr[jp][2]);
                    }
            }
            __syncthreads();
        }

        // fold expert e: accf += w[row,e] * (acce + bias[col])
#pragma unroll
        for (int f = 0; f < 2; f++) {
            const int r1 = wm * 32 + f * 16 + (lane >> 2);
            const float w1 = w_s[e][r1], w2 = w_s[e][r1 + 8];
#pragma unroll
            for (int j = 0; j < 4; j++) {
                const int c0 = wn * 32 + j * 8 + (lane & 3) * 2;
                const float b0 = bs_s[e][c0], b1 = bs_s[e][c0 + 1];
                accf[f][j][0] = fmaf(w1, acce[f][j][0] + b0, accf[f][j][0]);
                accf[f][j][1] = fmaf(w1, acce[f][j][1] + b1, accf[f][j][1]);
                accf[f][j][2] = fmaf(w2, acce[f][j][2] + b0, accf[f][j][2]);
                accf[f][j][3] = fmaf(w2, acce[f][j][3] + b1, accf[f][j][3]);
            }
        }
    }

    // write to per-group scratch
#pragma unroll
    for (int f = 0; f < 2; f++) {
        const int r1 = row0 + wm * 32 + f * 16 + (lane >> 2);
#pragma unroll
        for (int j = 0; j < 4; j++) {
            const int c0 = wn * 32 + j * 8 + (lane & 3) * 2;
            float* base = g_scratch + (size_t)eg * BDIM * ADIM;
            *(float2*)&base[(size_t)r1 * ADIM + c0] =
                make_float2(accf[f][j][0], accf[f][j][1]);
            *(float2*)&base[(size_t)(r1 + 8) * ADIM + c0] =
                make_float2(accf[f][j][2], accf[f][j][3]);
        }
    }
}

// ---------------------------------------------------------------------------
// Final reduce: out = sum over 8 expert-group partials
// ---------------------------------------------------------------------------
__global__ __launch_bounds__(256) void reduce_kernel(float* __restrict__ out) {
    const size_t idx = (size_t)blockIdx.x * 256 + threadIdx.x;
    const float4* s = (const float4*)g_scratch;
    float4 a = s[idx];
#pragma unroll
    for (int g = 1; g < NGRP; g++) {
        float4 t = s[(size_t)g * (BDIM * ADIM / 4) + idx];
        a.x += t.x; a.y += t.y; a.z += t.z; a.w += t.w;
    }
    ((float4*)out)[idx] = a;
}

// ---------------------------------------------------------------------------
extern "C" void kernel_launch(void* const* d_in, const int* in_sizes, int n_in,
                              void* d_out, int out_size) {
    const float* x             = (const float*)d_in[0];
    const float* W_att         = (const float*)d_in[1];
    const float* b_att         = (const float*)d_in[2];
    const float* adaptive_bias = (const float*)d_in[3];
    const float* W_strat       = (const float*)d_in[4];
    const float* b_strat       = (const float*)d_in[5];
    const float* gumbel_u      = (const float*)d_in[6];
    float* out = (float*)d_out;

    cudaFuncSetAttribute(gemm_tf32, cudaFuncAttributeMaxDynamicSharedMemorySize, SMEM_DYN);

    gating_kernel<<<BDIM / 8, 256>>>(x, W_att, b_att, adaptive_bias, gumbel_u);
    convert_x_tf<<<(BDIM * DDIM / 4) / 256, 256>>>(x);
    convert_w_tf<<<(EDIM * ADIM * DDIM / 4) / 256, 256>>>(W_strat);
    gemm_tf32<<<(BDIM / BM) * NGRP, THREADS, SMEM_DYN>>>(b_strat);
    reduce_kernel<<<(BDIM * ADIM / 4) / 256, 256>>>(out);
}

// round 8
// speedup vs baseline: 5.2514x; 1.0636x over previous
#include <cuda_runtime.h>
#include <cstdint>

#define BDIM 8192
#define DDIM 1024
#define EDIM 32
#define ADIM 128
#define EG   4
#define NGRP (EDIM / EG)     // 8
#define BM   128
#define BN   128
#define BK   32              // 32 fp32 = 128 B per smem row (SW128 atom width)
#define NKB  (DDIM / BK)     // 32
#define THREADS 512
#define TILE_BYTES (BM * BK * 4)             // 16384
#define STAGE      ((1 + EG) * TILE_BYTES)   // A + 4 B tiles = 81920
#define SMEM_DYN   (2 * STAGE)               // 163840 double buffered

// ---------------- device scratch (static; no allocs allowed) ----------------
__device__ __align__(1024) float g_Xtf[(size_t)BDIM * DDIM];          // tf32-rounded x
__device__ __align__(1024) float g_Wtf[(size_t)EDIM * ADIM * DDIM];   // tf32-rounded W_strat
__device__ float g_weights[BDIM * EDIM];
__device__ float g_scratch[(size_t)NGRP * BDIM * ADIM];

// ---------------- helpers ----------------
__device__ __forceinline__ uint32_t smem_u32(const void* p) {
    uint32_t a;
    asm("{ .reg .u64 t; cvta.to.shared.u64 t, %1; cvt.u32.u64 %0, t; }" : "=r"(a) : "l"(p));
    return a;
}
__device__ __forceinline__ void cp_async16(uint32_t dst, const void* src) {
    asm volatile("cp.async.cg.shared.global [%0], [%1], 16;" :: "r"(dst), "l"(src));
}
__device__ __forceinline__ void cp_commit() { asm volatile("cp.async.commit_group;"); }
__device__ __forceinline__ void cp_wait0()  { asm volatile("cp.async.wait_group 0;" ::: "memory"); }
__device__ __forceinline__ void cp_wait1()  { asm volatile("cp.async.wait_group 1;" ::: "memory"); }
__device__ __forceinline__ uint32_t sw128(uint32_t o) { return o ^ ((o >> 3) & 0x70); }
__device__ __forceinline__ uint32_t f2tf32(float v) {
    uint32_t t;
    asm("cvt.rna.tf32.f32 %0, %1;" : "=r"(t) : "f"(v));
    return t;
}
__device__ __forceinline__ void mma_tf32(float d[4], const uint32_t a[4], const uint32_t b[2]) {
    asm volatile(
        "mma.sync.aligned.m16n8k8.row.col.f32.tf32.tf32.f32 "
        "{%0,%1,%2,%3}, {%4,%5,%6,%7}, {%8,%9}, {%0,%1,%2,%3};"
        : "+f"(d[0]), "+f"(d[1]), "+f"(d[2]), "+f"(d[3])
        : "r"(a[0]), "r"(a[1]), "r"(a[2]), "r"(a[3]), "r"(b[0]), "r"(b[1]));
}

// ---------------------------------------------------------------------------
// Gating: logits + gumbel + softmax -> g_weights
// ---------------------------------------------------------------------------
__global__ __launch_bounds__(256) void gating_kernel(
    const float* __restrict__ x, const float* __restrict__ W_att,
    const float* __restrict__ b_att, const float* __restrict__ adaptive_bias,
    const float* __restrict__ gumbel_u)
{
    const int warp = threadIdx.x >> 5, lane = threadIdx.x & 31;
    const int b = blockIdx.x * 8 + warp;
    __shared__ float logits_s[8][EDIM];

    const float* xrow = x + (size_t)b * DDIM;
    float xr[32];
#pragma unroll
    for (int k = 0; k < 32; k++) xr[k] = xrow[k * 32 + lane];

    for (int e = 0; e < EDIM; e++) {
        const float* wrow = W_att + (size_t)e * DDIM;
        float p = 0.f;
#pragma unroll
        for (int k = 0; k < 32; k++) p = fmaf(xr[k], wrow[k * 32 + lane], p);
#pragma unroll
        for (int o = 16; o; o >>= 1) p += __shfl_xor_sync(0xffffffffu, p, o);
        if (lane == 0) logits_s[warp][e] = p;
    }
    __syncwarp();

    float l = logits_s[warp][lane] + b_att[lane] + adaptive_bias[lane];
    float u = gumbel_u[(size_t)b * EDIM + lane];
    float g = -logf(-logf(u + 1e-10f) + 1e-10f);
    float z = l + g;
    float m = z;
#pragma unroll
    for (int o = 16; o; o >>= 1) m = fmaxf(m, __shfl_xor_sync(0xffffffffu, m, o));
    float p = expf(z - m);
    float s = p;
#pragma unroll
    for (int o = 16; o; o >>= 1) s += __shfl_xor_sync(0xffffffffu, s, o);
    g_weights[(size_t)b * EDIM + lane] = p / s;
}

// ---------------------------------------------------------------------------
// Pre-round x and W_strat to tf32 precision (stored as f32 bits)
// ---------------------------------------------------------------------------
__global__ __launch_bounds__(256) void convert_x_tf(const float* __restrict__ x) {
    const size_t i4 = (size_t)blockIdx.x * 256 + threadIdx.x;
    float4 v = ((const float4*)x)[i4];
    uint4 o;
    o.x = f2tf32(v.x); o.y = f2tf32(v.y); o.z = f2tf32(v.z); o.w = f2tf32(v.w);
    ((uint4*)g_Xtf)[i4] = o;
}
__global__ __launch_bounds__(256) void convert_w_tf(const float* __restrict__ W_strat) {
    const size_t i4 = (size_t)blockIdx.x * 256 + threadIdx.x;
    float4 v = ((const float4*)W_strat)[i4];
    uint4 o;
    o.x = f2tf32(v.x); o.y = f2tf32(v.y); o.z = f2tf32(v.z); o.w = f2tf32(v.w);
    ((uint4*)g_Wtf)[i4] = o;
}

// ---------------------------------------------------------------------------
// TF32 mma.sync GEMM, fused epilogue, A-fragment reuse across experts.
// CTA = (mt, eg): 128 rows x 128 A-cols x 4 experts.
// Per kb: stage A + 4 expert B tiles; A fragments loaded once (32 regs),
// reused by all 4 experts; per-expert partial folded into accf with gating
// weight each kb (linear => exact same result as folding at the end).
// ---------------------------------------------------------------------------
__global__ __launch_bounds__(THREADS, 1) void gemm_tf32(const float* __restrict__ b_strat) {
    extern __shared__ char sm[];
    __shared__ float bs_s[EG][BN];
    __shared__ float w_s[EG][BM];

    const int tid = threadIdx.x, wid = tid >> 5, lane = tid & 31;
    const int wm = wid & 3, wn = wid >> 2;          // warp grid 4m x 4n
    const int eg = blockIdx.x & (NGRP - 1);
    const int mt = blockIdx.x >> 3;
    const int row0 = mt * BM;

    // stage bias + gating weights (EG*128 = 512 elements each, one per thread)
    {
        (&bs_s[0][0])[tid] = b_strat[(size_t)(eg * EG) * ADIM + tid];
        const int e = tid >> 7, r = tid & 127;
        w_s[e][r] = g_weights[(size_t)(row0 + r) * EDIM + eg * EG + e];
    }

    const uint32_t sbase = smem_u32(sm);

    // stage layout: A at +0 (16KB), B_e at +16384*(1+e)
    auto load_stage = [&](int b, int kb) {
        const uint32_t ab = sbase + b * STAGE;
        const char* xs = (const char*)g_Xtf + ((size_t)row0 * DDIM + kb * BK) * 4;
#pragma unroll
        for (int i = 0; i < 2; i++) {
            const int q = tid + THREADS * i, r = q >> 3, ch = (q & 7) * 16;
            cp_async16(ab + sw128(r * 128 + ch), xs + (size_t)r * DDIM * 4 + ch);
        }
#pragma unroll
        for (int e = 0; e < EG; e++) {
            const uint32_t bb = ab + (1 + e) * TILE_BYTES;
            const char* ws = (const char*)g_Wtf +
                             ((size_t)(eg * EG + e) * ADIM * DDIM + kb * BK) * 4;
#pragma unroll
            for (int i = 0; i < 2; i++) {
                const int q = tid + THREADS * i, r = q >> 3, ch = (q & 7) * 16;
                cp_async16(bb + sw128(r * 128 + ch), ws + (size_t)r * DDIM * 4 + ch);
            }
        }
        cp_commit();
    };

    float accf[2][4][4];
#pragma unroll
    for (int f = 0; f < 2; f++)
#pragma unroll
        for (int j = 0; j < 4; j++)
#pragma unroll
            for (int d = 0; d < 4; d++) accf[f][j][d] = 0.f;

    load_stage(0, 0);

    for (int kb = 0; kb < NKB; kb++) {
        const int buf = kb & 1;
        const bool more = (kb + 1 < NKB);
        if (more) load_stage(buf ^ 1, kb + 1);
        if (more) cp_wait1(); else cp_wait0();
        __syncthreads();

        const uint32_t ab = sbase + buf * STAGE;

        // A fragments for all 4 ks, loaded ONCE per kb, reused by 4 experts
        uint32_t afr[4][2][4];
#pragma unroll
        for (int ks = 0; ks < 4; ks++)
#pragma unroll
            for (int f = 0; f < 2; f++) {
                const int m0 = wm * 32 + f * 16;
                const uint32_t row = m0 + (lane & 15);
                const uint32_t byt = ks * 32 + (lane >> 4) * 16;
                const uint32_t addr = ab + sw128(row * 128 + byt);
                asm volatile(
                    "ldmatrix.sync.aligned.m8n8.x4.shared.b16 {%0,%1,%2,%3}, [%4];"
                    : "=r"(afr[ks][f][0]), "=r"(afr[ks][f][1]),
                      "=r"(afr[ks][f][2]), "=r"(afr[ks][f][3])
                    : "r"(addr));
            }

#pragma unroll
        for (int e = 0; e < EG; e++) {
            const uint32_t bb = ab + (1 + e) * TILE_BYTES;
            float acce[2][4][4];
#pragma unroll
            for (int f = 0; f < 2; f++)
#pragma unroll
                for (int j = 0; j < 4; j++)
#pragma unroll
                    for (int d = 0; d < 4; d++) acce[f][j][d] = 0.f;

#pragma unroll
            for (int ks = 0; ks < 4; ks++) {
                uint32_t bfr[2][4];
#pragma unroll
                for (int jp = 0; jp < 2; jp++) {
                    const int n0 = wn * 32 + jp * 16;
                    const uint32_t row = n0 + ((lane >> 4) & 1) * 8 + (lane & 7);
                    const uint32_t byt = ks * 32 + ((lane >> 3) & 1) * 16;
                    const uint32_t addr = bb + sw128(row * 128 + byt);
                    asm volatile(
                        "ldmatrix.sync.aligned.m8n8.x4.shared.b16 {%0,%1,%2,%3}, [%4];"
                        : "=r"(bfr[jp][0]), "=r"(bfr[jp][1]), "=r"(bfr[jp][2]), "=r"(bfr[jp][3])
                        : "r"(addr));
                }
#pragma unroll
                for (int f = 0; f < 2; f++)
#pragma unroll
                    for (int jp = 0; jp < 2; jp++) {
                        mma_tf32(acce[f][2 * jp + 0], afr[ks][f], &bfr[jp][0]);
                        mma_tf32(acce[f][2 * jp + 1], afr[ks][f], &bfr[jp][2]);
                    }
            }

            // fold this kb's partial for expert e (bias handled once at end)
#pragma unroll
            for (int f = 0; f < 2; f++) {
                const int r1 = wm * 32 + f * 16 + (lane >> 2);
                const float w1 = w_s[e][r1], w2 = w_s[e][r1 + 8];
#pragma unroll
                for (int j = 0; j < 4; j++) {
                    accf[f][j][0] = fmaf(w1, acce[f][j][0], accf[f][j][0]);
                    accf[f][j][1] = fmaf(w1, acce[f][j][1], accf[f][j][1]);
                    accf[f][j][2] = fmaf(w2, acce[f][j][2], accf[f][j][2]);
                    accf[f][j][3] = fmaf(w2, acce[f][j][3], accf[f][j][3]);
                }
            }
        }
        __syncthreads();
    }

    // add bias term: accf += sum_e w[row,e] * bias[e,col]
#pragma unroll
    for (int e = 0; e < EG; e++) {
#pragma unroll
        for (int f = 0; f < 2; f++) {
            const int r1 = wm * 32 + f * 16 + (lane >> 2);
            const float w1 = w_s[e][r1], w2 = w_s[e][r1 + 8];
#pragma unroll
            for (int j = 0; j < 4; j++) {
                const int c0 = wn * 32 + j * 8 + (lane & 3) * 2;
                const float b0 = bs_s[e][c0], b1 = bs_s[e][c0 + 1];
                accf[f][j][0] = fmaf(w1, b0, accf[f][j][0]);
                accf[f][j][1] = fmaf(w1, b1, accf[f][j][1]);
                accf[f][j][2] = fmaf(w2, b0, accf[f][j][2]);
                accf[f][j][3] = fmaf(w2, b1, accf[f][j][3]);
            }
        }
    }

    // write to per-group scratch
#pragma unroll
    for (int f = 0; f < 2; f++) {
        const int r1 = row0 + wm * 32 + f * 16 + (lane >> 2);
#pragma unroll
        for (int j = 0; j < 4; j++) {
            const int c0 = wn * 32 + j * 8 + (lane & 3) * 2;
            float* base = g_scratch + (size_t)eg * BDIM * ADIM;
            *(float2*)&base[(size_t)r1 * ADIM + c0] =
                make_float2(accf[f][j][0], accf[f][j][1]);
            *(float2*)&base[(size_t)(r1 + 8) * ADIM + c0] =
                make_float2(accf[f][j][2], accf[f][j][3]);
        }
    }
}

// ---------------------------------------------------------------------------
// Final reduce: out = sum over 8 expert-group partials
// ---------------------------------------------------------------------------
__global__ __launch_bounds__(256) void reduce_kernel(float* __restrict__ out) {
    const size_t idx = (size_t)blockIdx.x * 256 + threadIdx.x;
    const float4* s = (const float4*)g_scratch;
    float4 a = s[idx];
#pragma unroll
    for (int g = 1; g < NGRP; g++) {
        float4 t = s[(size_t)g * (BDIM * ADIM / 4) + idx];
        a.x += t.x; a.y += t.y; a.z += t.z; a.w += t.w;
    }
    ((float4*)out)[idx] = a;
}

// ---------------------------------------------------------------------------
extern "C" void kernel_launch(void* const* d_in, const int* in_sizes, int n_in,
                              void* d_out, int out_size) {
    const float* x             = (const float*)d_in[0];
    const float* W_att         = (const float*)d_in[1];
    const float* b_att         = (const float*)d_in[2];
    const float* adaptive_bias = (const float*)d_in[3];
    const float* W_strat       = (const float*)d_in[4];
    const float* b_strat       = (const float*)d_in[5];
    const float* gumbel_u      = (const float*)d_in[6];
    float* out = (float*)d_out;

    cudaFuncSetAttribute(gemm_tf32, cudaFuncAttributeMaxDynamicSharedMemorySize, SMEM_DYN);

    gating_kernel<<<BDIM / 8, 256>>>(x, W_att, b_att, adaptive_bias, gumbel_u);
    convert_x_tf<<<(BDIM * DDIM / 4) / 256, 256>>>(x);
    convert_w_tf<<<(EDIM * ADIM * DDIM / 4) / 256, 256>>>(W_strat);
    gemm_tf32<<<(BDIM / BM) * NGRP, THREADS, SMEM_DYN>>>(b_strat);
    reduce_kernel<<<(BDIM * ADIM / 4) / 256, 256>>>(out);
}